// round 12
// baseline (speedup 1.0000x reference)
#include <cuda_runtime.h>
#include <cuda_bf16.h>
#include <stdint.h>

#define BROWS 256
#define DDIM  1024
#define HDIM  2048
#define NOUT  2048   // 2*D

// ---------------- scratch (__device__ globals; no allocation allowed) ----------
__device__ __nv_bfloat16  g_mubf[BROWS * DDIM];
__device__ __nv_bfloat16  g_w1bf[DDIM * HDIM];   // [k=1024][n=2048]
__device__ __nv_bfloat16  g_w2bf[HDIM * NOUT];   // [k=2048][n=2048]
__device__ __nv_bfloat16  g_h[BROWS * HDIM];
__device__ float g_sg[BROWS], g_r[BROWS], g_wgt[BROWS];
__device__ int   g_lowt[BROWS];
__device__ float g_partial[128];
__device__ int   g_count;

// ---------------- PTX helpers ----------------------------------------------------
__device__ __forceinline__ uint32_t cvta_shared_u32(const void* p) {
    uint32_t a;
    asm("{ .reg .u64 t; cvta.to.shared.u64 t, %1; cvt.u32.u64 %0, t; }"
        : "=r"(a) : "l"(p));
    return a;
}
__device__ __forceinline__ void cpa16(uint32_t dst, const void* src) {
    asm volatile("cp.async.cg.shared.global [%0], [%1], 16;\n" :: "r"(dst), "l"(src));
}
__device__ __forceinline__ void ldm_x4(uint32_t* r, uint32_t addr) {
    asm volatile("ldmatrix.sync.aligned.m8n8.x4.shared.b16 {%0,%1,%2,%3}, [%4];\n"
                 : "=r"(r[0]), "=r"(r[1]), "=r"(r[2]), "=r"(r[3]) : "r"(addr));
}
__device__ __forceinline__ void ldm_x4t(uint32_t* r, uint32_t addr) {
    asm volatile("ldmatrix.sync.aligned.m8n8.x4.trans.shared.b16 {%0,%1,%2,%3}, [%4];\n"
                 : "=r"(r[0]), "=r"(r[1]), "=r"(r[2]), "=r"(r[3]) : "r"(addr));
}
__device__ __forceinline__ void mma16816(float* c, const uint32_t* a, const uint32_t* b) {
    asm volatile(
        "mma.sync.aligned.m16n8k16.row.col.f32.bf16.bf16.f32 "
        "{%0,%1,%2,%3}, {%4,%5,%6,%7}, {%8,%9}, {%0,%1,%2,%3};\n"
        : "+f"(c[0]), "+f"(c[1]), "+f"(c[2]), "+f"(c[3])
        : "r"(a[0]), "r"(a[1]), "r"(a[2]), "r"(a[3]), "r"(b[0]), "r"(b[1]));
}

// ---------------- fast erf (Abramowitz-Stegun 7.1.26, |err| <= 1.5e-7) ----------
__device__ __forceinline__ float erf_fast_e(float x, float e /* = exp(-x*x) */) {
    float ax = fabsf(x);
    float t = __fdividef(1.0f, fmaf(0.3275911f, ax, 1.0f));
    float p = fmaf(fmaf(fmaf(fmaf(1.061405429f, t, -1.453152027f), t,
                             1.421413741f), t, -0.284496736f), t, 0.254829592f) * t;
    return copysignf(1.0f - p * e, x);
}
__device__ __forceinline__ float erf_fast(float x) {
    return erf_fast_e(x, __expf(-x * x));
}

// ---------------- EM-telescoped discretised-CDF loss for one element -------------
__device__ __forceinline__ float loss_elem(float me, float ls, float xv, float mug,
                                           float r, float w, int lowt) {
    const float IRP  = 0.5641895835f;
    const float CH24 = 1.1283791671f / 24.0f;
    const float CH3  = 7.0f * 1.1283791671f / 5760.0f;
    float mu_x = mug - r * me;
    float sx = r * __expf(ls);
    if (lowt) { mu_x = 0.f; sx = 1.f; }
    float inv  = 0.70710678118654752f / sx;
    float base = (-1.0f - mu_x) * inv;
    float h    = 0.015625f * inv;
    float S;
    if (h > 0.5f) {
        float center = 64.f * (1.f + mu_x);
        float halfw  = 256.f / inv;
        int klo = (int)ceilf(center - halfw);
        int khi = (int)floorf(center + halfw);
        klo = klo < 1 ? 1 : (klo > 127 ? 127 : klo);
        khi = khi < 0 ? 0 : (khi > 126 ? 126 : khi);
        S = (float)(126 - khi) - (float)(klo - 1);
        for (int k = klo; k <= khi; ++k)
            S += erf_fast(fmaf((float)k, h, base));
    } else {
        float a  = fmaf(0.5f,   h, base);
        float bq = fmaf(126.5f, h, base);
        float ea = __expf(-a * a);
        float eb = __expf(-bq * bq);
        float efa = erf_fast_e(a, ea), efb = erf_fast_e(bq, eb);
        float I = (bq * efb - a * efa) + IRP * (eb - ea);
        float rcp = 90.50966799f * sx;
        S = I * rcp
          - (h * CH24) * (eb - ea)
          + (h * h * h * CH3) * (fmaf(4.f * bq, bq, -2.f) * eb
                                 - fmaf(4.f * a, a, -2.f) * ea);
    }
    float G127 = 0.5f + 0.5f * erf_fast(fmaf(127.f, h, base));
    float pO = 0.9765625f * G127 - 0.015625f * (63.f + 0.5f * S);
    float diff = xv - pO;
    return w * diff * diff;
}

// ---------------- prep: mubf + row scalars + W1/W2 converts ----------------------
__device__ __forceinline__ void conv8(const float* __restrict__ src,
                                      __nv_bfloat16* __restrict__ dst, int i) {
    float4 v0 = ((const float4*)src)[2 * i];
    float4 v1 = ((const float4*)src)[2 * i + 1];
    __nv_bfloat162 o[4];
    o[0] = __floats2bfloat162_rn(v0.x, v0.y);
    o[1] = __floats2bfloat162_rn(v0.z, v0.w);
    o[2] = __floats2bfloat162_rn(v1.x, v1.y);
    o[3] = __floats2bfloat162_rn(v1.z, v1.w);
    ((uint4*)dst)[i] = *(uint4*)o;
}

__global__ void __launch_bounds__(256) prep_k(const float* __restrict__ x,
                                              const float* __restrict__ noise,
                                              const float* __restrict__ t,
                                              const float* __restrict__ W1,
                                              const float* __restrict__ W2) {
    int blk = blockIdx.x;
    if (blk < 256) {
        int i4 = blk * 256 + threadIdx.x;
        int b = i4 >> 8;
        float tv = __ldg(&t[b]);
        float sg = expf(-7.824046010856292f * tv);
        float gamma = 1.0f - sg;
        float4 xv = ((const float4*)x)[i4];
        float4 nv = ((const float4*)noise)[i4];
        __nv_bfloat162 o[2];
        o[0] = __floats2bfloat162_rn(gamma * fmaf(sg, nv.x, xv.x),
                                     gamma * fmaf(sg, nv.y, xv.y));
        o[1] = __floats2bfloat162_rn(gamma * fmaf(sg, nv.z, xv.z),
                                     gamma * fmaf(sg, nv.w, xv.w));
        ((uint2*)g_mubf)[i4] = *(uint2*)o;
        if (blk == 0) {
            int bb = threadIdx.x;
            float tb = t[bb];
            float s2 = expf(-7.824046010856292f * tb);
            float g2 = 1.0f - s2;
            g_sg[bb]   = s2;
            g_r[bb]    = sqrtf(s2 / g2);
            g_wgt[bb]  = 1.0f / s2;
            g_lowt[bb] = (tb < 1e-10f) ? 1 : 0;
            if (bb == 0) g_count = 0;
        }
        return;
    }
    if (blk < 1280) { conv8(W1, g_w1bf, (blk - 256) * 256 + threadIdx.x); return; }
    conv8(W2, g_w2bf, (blk - 1280) * 256 + threadIdx.x);
}

// ---------------- GEMM1 (R6 config): BM=BN=BK=64, 256 thr ------------------------
#define PITCH_B 144
#define STAGE_A (64 * PITCH_B)
#define STAGE_BYTES (2 * 64 * PITCH_B)

__global__ void __launch_bounds__(256) gemm1_k(const float* __restrict__ bias,
                                               const float* __restrict__ tvec,
                                               const float* __restrict__ w1last) {
    extern __shared__ char smem[];
    uint32_t sbase = cvta_shared_u32(smem);
    int tid = threadIdx.x, wid = tid >> 5, lane = tid & 31;
    int m0 = blockIdx.y * 64, n0 = blockIdx.x * 64;
    int wm = (wid >> 2) * 32, wn = (wid & 3) * 16;

    float c[2][2][4];
    #pragma unroll
    for (int mf = 0; mf < 2; ++mf)
        #pragma unroll
        for (int nb = 0; nb < 2; ++nb)
            #pragma unroll
            for (int j = 0; j < 4; ++j) c[mf][nb][j] = 0.f;

    auto issue = [&](int tt) {
        uint32_t sA = sbase + (uint32_t)(tt % 3) * STAGE_BYTES;
        uint32_t sB = sA + STAGE_A;
        int k0 = tt << 6;
        #pragma unroll
        for (int i = 0; i < 2; ++i) {
            int id = tid + i * 256;
            int row = id >> 3, c16 = id & 7;
            cpa16(sA + (uint32_t)(row * PITCH_B + c16 * 16),
                  g_mubf + (size_t)(m0 + row) * DDIM + k0 + c16 * 8);
        }
        #pragma unroll
        for (int i = 0; i < 2; ++i) {
            int id = tid + i * 256;
            int row = id >> 3, c16 = id & 7;
            cpa16(sB + (uint32_t)(row * PITCH_B + c16 * 16),
                  g_w1bf + (size_t)(k0 + row) * 2048 + n0 + c16 * 8);
        }
        asm volatile("cp.async.commit_group;\n" ::: "memory");
    };

    issue(0); issue(1);
    for (int tt = 0; tt < 16; ++tt) {
        asm volatile("cp.async.wait_group 1;\n" ::: "memory");
        __syncthreads();
        if (tt + 2 < 16) issue(tt + 2);
        else asm volatile("cp.async.commit_group;\n" ::: "memory");

        uint32_t sA = sbase + (uint32_t)(tt % 3) * STAGE_BYTES;
        uint32_t sB = sA + STAGE_A;
        #pragma unroll
        for (int ks = 0; ks < 4; ++ks) {
            uint32_t a[2][4], b[4];
            #pragma unroll
            for (int mf = 0; mf < 2; ++mf)
                ldm_x4(a[mf], sA + (uint32_t)((wm + mf * 16 + (lane & 15)) * PITCH_B
                                              + (ks * 16 + ((lane >> 4) << 3)) * 2));
            ldm_x4t(b, sB + (uint32_t)((ks * 16 + (lane & 15)) * PITCH_B
                                       + (wn + ((lane >> 4) << 3)) * 2));
            #pragma unroll
            for (int mf = 0; mf < 2; ++mf) {
                mma16816(c[mf][0], a[mf], &b[0]);
                mma16816(c[mf][1], a[mf], &b[2]);
            }
        }
    }

    int tc = lane & 3, gr = lane >> 2;
    #pragma unroll
    for (int mf = 0; mf < 2; ++mf)
        #pragma unroll
        for (int nb = 0; nb < 2; ++nb) {
            int col = n0 + wn + nb * 8 + tc * 2;
            #pragma unroll
            for (int half = 0; half < 2; ++half) {
                int row = m0 + wm + mf * 16 + gr + half * 8;
                float tw = tvec[row];
                float v0 = c[mf][nb][half * 2 + 0] + bias[col]     + tw * w1last[col];
                float v1 = c[mf][nb][half * 2 + 1] + bias[col + 1] + tw * w1last[col + 1];
                v0 = (v0 >= 0.f) ? v0 : 0.01f * v0;
                v1 = (v1 >= 0.f) ? v1 : 0.01f * v1;
                *(__nv_bfloat162*)&g_h[(size_t)row * HDIM + col] =
                    __floats2bfloat162_rn(v0, v1);
            }
        }
}

// ---------------- GEMM2 + fused loss ---------------------------------------------
// 512 threads = 2 groups x 8 warps. Group g computes K-half g over the SAME 64x64
// output tile. Paired columns: smem cols [0,32) = global [32bx,32bx+32) (mu_eps),
// cols [32,64) = global [1024+32bx, ...) (ln_sig). After mainloop the two groups
// store partial tiles to smem; all 512 threads then compute the loss in-place.
#define TILE_PITCH 66

__global__ void __launch_bounds__(512) gemm2_fused_k(const float* __restrict__ bias,
                                                     const float* __restrict__ x,
                                                     const float* __restrict__ noise,
                                                     float* __restrict__ out) {
    extern __shared__ char smem[];
    uint32_t sbase = cvta_shared_u32(smem);
    int tid = threadIdx.x;
    int group = tid >> 8, gt = tid & 255;
    int wid = gt >> 5, lane = tid & 31;
    int m0 = blockIdx.y * 64;
    int n0p = blockIdx.x * 32;
    int koff = group << 10;
    int wm = (wid >> 2) * 32, wn = (wid & 3) * 16;
    uint32_t gbase = sbase + (uint32_t)group * (3 * STAGE_BYTES);

    float c[2][2][4];
    #pragma unroll
    for (int mf = 0; mf < 2; ++mf)
        #pragma unroll
        for (int nb = 0; nb < 2; ++nb)
            #pragma unroll
            for (int j = 0; j < 4; ++j) c[mf][nb][j] = 0.f;

    auto issue = [&](int tt) {
        uint32_t sA = gbase + (uint32_t)(tt % 3) * STAGE_BYTES;
        uint32_t sB = sA + STAGE_A;
        int k0 = (tt << 6) + koff;
        #pragma unroll
        for (int i = 0; i < 2; ++i) {
            int id = gt + i * 256;
            int row = id >> 3, c16 = id & 7;
            cpa16(sA + (uint32_t)(row * PITCH_B + c16 * 16),
                  g_h + (size_t)(m0 + row) * HDIM + k0 + c16 * 8);
        }
        #pragma unroll
        for (int i = 0; i < 2; ++i) {
            int id = gt + i * 256;
            int row = id >> 3, c16 = id & 7;
            int gcol = (c16 < 4) ? (n0p + c16 * 8) : (1024 + n0p + (c16 - 4) * 8);
            cpa16(sB + (uint32_t)(row * PITCH_B + c16 * 16),
                  g_w2bf + (size_t)(k0 + row) * 2048 + gcol);
        }
        asm volatile("cp.async.commit_group;\n" ::: "memory");
    };

    issue(0); issue(1);
    for (int tt = 0; tt < 16; ++tt) {
        asm volatile("cp.async.wait_group 1;\n" ::: "memory");
        __syncthreads();
        if (tt + 2 < 16) issue(tt + 2);
        else asm volatile("cp.async.commit_group;\n" ::: "memory");

        uint32_t sA = gbase + (uint32_t)(tt % 3) * STAGE_BYTES;
        uint32_t sB = sA + STAGE_A;
        #pragma unroll
        for (int ks = 0; ks < 4; ++ks) {
            uint32_t a[2][4], b[4];
            #pragma unroll
            for (int mf = 0; mf < 2; ++mf)
                ldm_x4(a[mf], sA + (uint32_t)((wm + mf * 16 + (lane & 15)) * PITCH_B
                                              + (ks * 16 + ((lane >> 4) << 3)) * 2));
            ldm_x4t(b, sB + (uint32_t)((ks * 16 + (lane & 15)) * PITCH_B
                                       + (wn + ((lane >> 4) << 3)) * 2));
            #pragma unroll
            for (int mf = 0; mf < 2; ++mf) {
                mma16816(c[mf][0], a[mf], &b[0]);
                mma16816(c[mf][1], a[mf], &b[2]);
            }
        }
    }
    __syncthreads();   // all mainloop smem reads done -> stages reusable as tiles

    // partial tiles: tileA (group 0, +bias) and tileB (group 1), 64 x 66 fp32 each
    float* tileA = (float*)smem;
    float* tileB = (float*)(smem + 17408);
    {
        float* mytile = group ? tileB : tileA;
        int tc = lane & 3, gr = lane >> 2;
        #pragma unroll
        for (int mf = 0; mf < 2; ++mf)
            #pragma unroll
            for (int nb = 0; nb < 2; ++nb) {
                int lcol = wn + nb * 8 + tc * 2;
                int bcol = (lcol < 32) ? (n0p + lcol) : (1024 + n0p + lcol - 32);
                #pragma unroll
                for (int half = 0; half < 2; ++half) {
                    int lrow = wm + mf * 16 + gr + half * 8;
                    float v0 = c[mf][nb][half * 2 + 0];
                    float v1 = c[mf][nb][half * 2 + 1];
                    if (group == 0) { v0 += bias[bcol]; v1 += bias[bcol + 1]; }
                    *(float2*)&mytile[lrow * TILE_PITCH + lcol] = make_float2(v0, v1);
                }
            }
    }
    __syncthreads();

    // fused loss: 2048 elements (64 rows x 32 paired cols), 4 per thread
    float acc = 0.f;
    {
        int lrow = tid >> 3;            // 0..63
        int c0 = (tid & 7) * 4;         // 0..28
        int grow = m0 + lrow;
        float sg = g_sg[grow], r = g_r[grow], w = g_wgt[grow];
        int lowt = g_lowt[grow];
        int xbase = grow * DDIM + n0p + c0;
        float4 xv4 = *(const float4*)&x[xbase];
        float4 nv4 = *(const float4*)&noise[xbase];
        const float* xp = &xv4.x;
        const float* np = &nv4.x;
        #pragma unroll
        for (int j = 0; j < 4; ++j) {
            float me = tileA[lrow * TILE_PITCH + c0 + j] + tileB[lrow * TILE_PITCH + c0 + j];
            float ls = tileA[lrow * TILE_PITCH + 32 + c0 + j] + tileB[lrow * TILE_PITCH + 32 + c0 + j];
            float mug = fmaf(sg, np[j], xp[j]);
            acc += loss_elem(me, ls, xp[j], mug, r, w, lowt);
        }
    }
    __syncthreads();   // tiles no longer needed; reuse smem for reduction

    float* red = (float*)(smem + 40960);
    red[tid] = acc;
    __syncthreads();
    #pragma unroll
    for (int s = 256; s > 0; s >>= 1) {
        if (tid < s) red[tid] += red[tid + s];
        __syncthreads();
    }
    int bid = blockIdx.y * 32 + blockIdx.x;
    if (tid == 0) g_partial[bid] = red[0];

    // last CTA reduces the 128 partials (deterministic order)
    __shared__ int amLast;
    __threadfence();
    if (tid == 0) amLast = (atomicAdd(&g_count, 1) == 127);
    __syncthreads();
    if (amLast) {
        double* dred = (double*)(smem + 43520);
        if (tid < 128) dred[tid] = (double)g_partial[tid];
        __syncthreads();
        #pragma unroll
        for (int st = 64; st > 0; st >>= 1) {
            if (tid < st) dred[tid] += dred[tid + st];
            __syncthreads();
        }
        if (tid == 0) {
            out[0] = (float)(3.912023005428146 * dred[0] / 262144.0);
            g_count = 0;
        }
    }
}

// ---------------- launch --------------------------------------------------------
extern "C" void kernel_launch(void* const* d_in, const int* in_sizes, int n_in,
                              void* d_out, int out_size) {
    const float* x     = (const float*)d_in[0];   // (256,1024)
    const float* t     = (const float*)d_in[1];   // (256,1)
    const float* noise = (const float*)d_in[2];   // (256,1024)
    const float* W1    = (const float*)d_in[3];   // (1025,2048)
    const float* b1    = (const float*)d_in[4];   // (2048,)
    const float* W2    = (const float*)d_in[5];   // (2048,2048)
    const float* b2    = (const float*)d_in[6];   // (2048,)

    size_t smem1 = 3 * STAGE_BYTES;       // 55296
    size_t smem2 = 6 * STAGE_BYTES;       // 110592
    cudaFuncSetAttribute(gemm1_k, cudaFuncAttributeMaxDynamicSharedMemorySize, (int)smem1);
    cudaFuncSetAttribute(gemm2_fused_k, cudaFuncAttributeMaxDynamicSharedMemorySize, (int)smem2);

    prep_k<<<3328, 256>>>(x, noise, t, W1, W2);

    dim3 g1(2048 / 64, BROWS / 64);       // (32, 4) = 128 CTAs
    gemm1_k<<<g1, 256, smem1>>>(b1, t, W1 + (size_t)DDIM * HDIM);

    dim3 g2(32, 4);                       // 128 CTAs, 512 threads each
    gemm2_fused_k<<<g2, 512, smem2>>>(b2, x, noise, (float*)d_out);
}

// round 13
// speedup vs baseline: 1.1087x; 1.1087x over previous
#include <cuda_runtime.h>
#include <cuda_bf16.h>
#include <stdint.h>

#define BROWS 256
#define DDIM  1024
#define HDIM  2048
#define NOUT  2048   // 2*D

// ---------------- scratch (__device__ globals; no allocation allowed) ----------
__device__ __nv_bfloat16  g_mubf[BROWS * DDIM];
__device__ __nv_bfloat16  g_w1bf[DDIM * HDIM];   // [k=1024][n=2048]
__device__ __nv_bfloat16  g_w2bf[HDIM * NOUT];   // [k=2048][n=2048]
__device__ __nv_bfloat16  g_h[BROWS * HDIM];
__device__ float          g_out[BROWS * NOUT];    // gemm2 z=0 partial (+bias)
__device__ float          g_out2[BROWS * NOUT];   // gemm2 z=1 partial
__device__ float g_sg[BROWS], g_r[BROWS], g_wgt[BROWS];
__device__ int   g_lowt[BROWS];
__device__ float g_partial[1024];
__device__ int   g_count;

// ---------------- PTX helpers ----------------------------------------------------
__device__ __forceinline__ uint32_t cvta_shared_u32(const void* p) {
    uint32_t a;
    asm("{ .reg .u64 t; cvta.to.shared.u64 t, %1; cvt.u32.u64 %0, t; }"
        : "=r"(a) : "l"(p));
    return a;
}
__device__ __forceinline__ void cpa16(uint32_t dst, const void* src) {
    asm volatile("cp.async.cg.shared.global [%0], [%1], 16;\n" :: "r"(dst), "l"(src));
}
__device__ __forceinline__ void ldm_x4(uint32_t* r, uint32_t addr) {
    asm volatile("ldmatrix.sync.aligned.m8n8.x4.shared.b16 {%0,%1,%2,%3}, [%4];\n"
                 : "=r"(r[0]), "=r"(r[1]), "=r"(r[2]), "=r"(r[3]) : "r"(addr));
}
__device__ __forceinline__ void ldm_x4t(uint32_t* r, uint32_t addr) {
    asm volatile("ldmatrix.sync.aligned.m8n8.x4.trans.shared.b16 {%0,%1,%2,%3}, [%4];\n"
                 : "=r"(r[0]), "=r"(r[1]), "=r"(r[2]), "=r"(r[3]) : "r"(addr));
}
__device__ __forceinline__ void mma16816(float* c, const uint32_t* a, const uint32_t* b) {
    asm volatile(
        "mma.sync.aligned.m16n8k16.row.col.f32.bf16.bf16.f32 "
        "{%0,%1,%2,%3}, {%4,%5,%6,%7}, {%8,%9}, {%0,%1,%2,%3};\n"
        : "+f"(c[0]), "+f"(c[1]), "+f"(c[2]), "+f"(c[3])
        : "r"(a[0]), "r"(a[1]), "r"(a[2]), "r"(a[3]), "r"(b[0]), "r"(b[1]));
}

// ---------------- fast erf (Abramowitz-Stegun 7.1.26, |err| <= 1.5e-7) ----------
__device__ __forceinline__ float erf_fast_e(float x, float e /* = exp(-x*x) */) {
    float ax = fabsf(x);
    float t = __fdividef(1.0f, fmaf(0.3275911f, ax, 1.0f));
    float p = fmaf(fmaf(fmaf(fmaf(1.061405429f, t, -1.453152027f), t,
                             1.421413741f), t, -0.284496736f), t, 0.254829592f) * t;
    return copysignf(1.0f - p * e, x);
}
__device__ __forceinline__ float erf_fast(float x) {
    return erf_fast_e(x, __expf(-x * x));
}

// ---------------- convert helper: 8 fp32 -> 8 bf16 per call ----------------------
__device__ __forceinline__ void conv8(const float* __restrict__ src,
                                      __nv_bfloat16* __restrict__ dst, int i) {
    float4 v0 = ((const float4*)src)[2 * i];
    float4 v1 = ((const float4*)src)[2 * i + 1];
    __nv_bfloat162 o[4];
    o[0] = __floats2bfloat162_rn(v0.x, v0.y);
    o[1] = __floats2bfloat162_rn(v0.z, v0.w);
    o[2] = __floats2bfloat162_rn(v1.x, v1.y);
    o[3] = __floats2bfloat162_rn(v1.z, v1.w);
    ((uint4*)dst)[i] = *(uint4*)o;
}

// ---------------- prep: 2 units/thread (MLP), mubf + scalars + W1/W2 converts ----
// blocks [0,128): mubf (2 float4/thread) ; [128,640): W1 ; [640,1664): W2
__global__ void __launch_bounds__(256) prep_k(const float* __restrict__ x,
                                              const float* __restrict__ noise,
                                              const float* __restrict__ t,
                                              const float* __restrict__ W1,
                                              const float* __restrict__ W2) {
    int blk = blockIdx.x;
    int tid = threadIdx.x;
    if (blk < 128) {
        #pragma unroll
        for (int it = 0; it < 2; ++it) {
            int i4 = (blk * 2 + it) * 256 + tid;   // 65536 float4s total
            int b = i4 >> 8;
            float tv = __ldg(&t[b]);
            float sg = expf(-7.824046010856292f * tv);
            float gamma = 1.0f - sg;
            float4 xv = ((const float4*)x)[i4];
            float4 nv = ((const float4*)noise)[i4];
            __nv_bfloat162 o[2];
            o[0] = __floats2bfloat162_rn(gamma * fmaf(sg, nv.x, xv.x),
                                         gamma * fmaf(sg, nv.y, xv.y));
            o[1] = __floats2bfloat162_rn(gamma * fmaf(sg, nv.z, xv.z),
                                         gamma * fmaf(sg, nv.w, xv.w));
            ((uint2*)g_mubf)[i4] = *(uint2*)o;
        }
        if (blk == 0) {
            int bb = tid;
            float tb = t[bb];
            float s2 = expf(-7.824046010856292f * tb);
            float g2 = 1.0f - s2;
            g_sg[bb]   = s2;
            g_r[bb]    = sqrtf(s2 / g2);
            g_wgt[bb]  = 1.0f / s2;
            g_lowt[bb] = (tb < 1e-10f) ? 1 : 0;
            if (bb == 0) g_count = 0;
        }
        return;
    }
    if (blk < 640) {                    // W1: 262144 conv8-units
        int base = (blk - 128) * 512 + tid;
        conv8(W1, g_w1bf, base);
        conv8(W1, g_w1bf, base + 256);
        return;
    }
    {                                   // W2: 524288 conv8-units
        int base = (blk - 640) * 512 + tid;
        conv8(W2, g_w2bf, base);
        conv8(W2, g_w2bf, base + 256);
    }
}

// ---------------- GEMM: BM=BN=BK=64, 256 thr, 4-stage cp.async -------------------
// MODE 1: A=g_mubf K=1024, B=g_w1bf. Epi: +b1 + t*W1last, leaky -> g_h (bf16)
// MODE 2: A=g_h lda=2048, split-K z in {0,1}, Klen=1024 each.
//         z=0 -> g_out (+bias), z=1 -> g_out2
#define PITCH_B 144
#define STAGE_A (64 * PITCH_B)
#define STAGE_BYTES (2 * 64 * PITCH_B)
#define NSTAGE 4

template <int MODE>
__global__ void __launch_bounds__(256) gemm_k(int lda,
                                              const float* __restrict__ bias,
                                              const float* __restrict__ tvec,
                                              const float* __restrict__ w1last) {
    extern __shared__ char smem[];
    uint32_t sbase = cvta_shared_u32(smem);

    const __nv_bfloat16* A = (MODE == 1) ? g_mubf : g_h;
    const __nv_bfloat16* B = (MODE == 1) ? g_w1bf : g_w2bf;

    int tid = threadIdx.x, wid = tid >> 5, lane = tid & 31;
    int m0 = blockIdx.y * 64, n0 = blockIdx.x * 64;
    int koff = (MODE == 2) ? (int)blockIdx.z * 1024 : 0;
    int wm = (wid >> 2) * 32;
    int wn = (wid & 3) * 16;

    float c[2][2][4];
    #pragma unroll
    for (int mf = 0; mf < 2; ++mf)
        #pragma unroll
        for (int nb = 0; nb < 2; ++nb)
            #pragma unroll
            for (int j = 0; j < 4; ++j) c[mf][nb][j] = 0.f;

    const int ntiles = 16;   // K=1024 per (split-)GEMM

    auto issue = [&](int tt) {
        uint32_t sA = sbase + (uint32_t)(tt % NSTAGE) * STAGE_BYTES;
        uint32_t sB = sA + STAGE_A;
        int k0 = (tt << 6) + koff;
        #pragma unroll
        for (int i = 0; i < 2; ++i) {
            int id = tid + i * 256;
            int row = id >> 3, c16 = id & 7;
            cpa16(sA + (uint32_t)(row * PITCH_B + c16 * 16),
                  A + (size_t)(m0 + row) * lda + k0 + c16 * 8);
        }
        #pragma unroll
        for (int i = 0; i < 2; ++i) {
            int id = tid + i * 256;
            int row = id >> 3, c16 = id & 7;
            cpa16(sB + (uint32_t)(row * PITCH_B + c16 * 16),
                  B + (size_t)(k0 + row) * 2048 + n0 + c16 * 8);
        }
        asm volatile("cp.async.commit_group;\n" ::: "memory");
    };

    issue(0); issue(1); issue(2);

    for (int tt = 0; tt < ntiles; ++tt) {
        asm volatile("cp.async.wait_group 2;\n" ::: "memory");
        __syncthreads();
        if (tt + 3 < ntiles) issue(tt + 3);
        else asm volatile("cp.async.commit_group;\n" ::: "memory");

        uint32_t sA = sbase + (uint32_t)(tt % NSTAGE) * STAGE_BYTES;
        uint32_t sB = sA + STAGE_A;
        #pragma unroll
        for (int ks = 0; ks < 4; ++ks) {
            uint32_t a[2][4], b[4];
            #pragma unroll
            for (int mf = 0; mf < 2; ++mf)
                ldm_x4(a[mf], sA + (uint32_t)((wm + mf * 16 + (lane & 15)) * PITCH_B
                                              + (ks * 16 + ((lane >> 4) << 3)) * 2));
            ldm_x4t(b, sB + (uint32_t)((ks * 16 + (lane & 15)) * PITCH_B
                                       + (wn + ((lane >> 4) << 3)) * 2));
            #pragma unroll
            for (int mf = 0; mf < 2; ++mf) {
                mma16816(c[mf][0], a[mf], &b[0]);
                mma16816(c[mf][1], a[mf], &b[2]);
            }
        }
    }

    // epilogue
    int tc = lane & 3, g = lane >> 2;
    #pragma unroll
    for (int mf = 0; mf < 2; ++mf)
        #pragma unroll
        for (int nb = 0; nb < 2; ++nb) {
            int col = n0 + wn + nb * 8 + tc * 2;
            #pragma unroll
            for (int half = 0; half < 2; ++half) {
                int row = m0 + wm + mf * 16 + g + half * 8;
                float v0 = c[mf][nb][half * 2 + 0];
                float v1 = c[mf][nb][half * 2 + 1];
                if (MODE == 1) {
                    float tw = tvec[row];
                    v0 += bias[col]     + tw * w1last[col];
                    v1 += bias[col + 1] + tw * w1last[col + 1];
                    v0 = (v0 >= 0.f) ? v0 : 0.01f * v0;
                    v1 = (v1 >= 0.f) ? v1 : 0.01f * v1;
                    *(__nv_bfloat162*)&g_h[(size_t)row * HDIM + col] =
                        __floats2bfloat162_rn(v0, v1);
                } else {
                    float* dst = (blockIdx.z == 0) ? g_out : g_out2;
                    if (blockIdx.z == 0) {
                        v0 += bias[col];
                        v1 += bias[col + 1];
                    }
                    *(float2*)&dst[(size_t)row * NOUT + col] = make_float2(v0, v1);
                }
            }
        }
}

// ---------------- loss + fused final reduction -----------------------------------
__global__ void __launch_bounds__(256) loss_k(const float* __restrict__ x,
                                              const float* __restrict__ noise,
                                              float* __restrict__ out) {
    int blk = blockIdx.x;            // 1024 blocks
    int tid = threadIdx.x;
    int b = blk >> 2;
    int d = ((blk & 3) << 8) + tid;  // 0..1023
    float sg = g_sg[b], r = g_r[b], w = g_wgt[b];
    int lowt = g_lowt[b];

    float me = g_out[b * NOUT + d]        + g_out2[b * NOUT + d];
    float ls = g_out[b * NOUT + DDIM + d] + g_out2[b * NOUT + DDIM + d];
    int idx = b * DDIM + d;
    float xv = x[idx];
    float mug = fmaf(sg, noise[idx], xv);   // mu / gamma

    const float IRP  = 0.5641895835f;          // 1/sqrt(pi)
    const float CH24 = 1.1283791671f / 24.0f;
    const float CH3  = 7.0f * 1.1283791671f / 5760.0f;

    float mu_x = mug - r * me;
    float sx = r * __expf(ls);
    if (lowt) { mu_x = 0.f; sx = 1.f; }
    float inv  = 0.70710678118654752f / sx;
    float base = (-1.0f - mu_x) * inv;
    float h    = 0.015625f * inv;

    float S;
    if (h > 0.5f) {
        float center = 64.f * (1.f + mu_x);
        float halfw  = 256.f / inv;
        int klo = (int)ceilf(center - halfw);
        int khi = (int)floorf(center + halfw);
        klo = klo < 1 ? 1 : (klo > 127 ? 127 : klo);
        khi = khi < 0 ? 0 : (khi > 126 ? 126 : khi);
        S = (float)(126 - khi) - (float)(klo - 1);
        for (int k = klo; k <= khi; ++k)
            S += erf_fast(fmaf((float)k, h, base));
    } else {
        float a  = fmaf(0.5f,   h, base);
        float bq = fmaf(126.5f, h, base);
        float ea = __expf(-a * a);
        float eb = __expf(-bq * bq);
        float efa = erf_fast_e(a, ea), efb = erf_fast_e(bq, eb);
        float I = (bq * efb - a * efa) + IRP * (eb - ea);
        float rcp = 90.50966799f * sx;   // 1/h
        S = I * rcp
          - (h * CH24) * (eb - ea)
          + (h * h * h * CH3) * (fmaf(4.f * bq, bq, -2.f) * eb
                                 - fmaf(4.f * a, a, -2.f) * ea);
    }

    float G127 = 0.5f + 0.5f * erf_fast(fmaf(127.f, h, base));
    float pO = 0.9765625f * G127 - 0.015625f * (63.f + 0.5f * S);
    float diff = xv - pO;
    float acc = w * diff * diff;

    __shared__ float red[256];
    red[tid] = acc;
    __syncthreads();
    #pragma unroll
    for (int s = 128; s > 0; s >>= 1) {
        if (tid < s) red[tid] += red[tid + s];
        __syncthreads();
    }
    if (tid == 0) g_partial[blk] = red[0];

    // fused final reduction: last block sums all partials (deterministic order)
    __shared__ int amLast;
    __threadfence();
    if (tid == 0) amLast = (atomicAdd(&g_count, 1) == 1023);
    __syncthreads();
    if (amLast) {
        __shared__ double dred[256];
        double s = 0.0;
        #pragma unroll
        for (int i = 0; i < 4; ++i) s += (double)g_partial[tid + i * 256];
        dred[tid] = s;
        __syncthreads();
        #pragma unroll
        for (int st = 128; st > 0; st >>= 1) {
            if (tid < st) dred[tid] += dred[tid + st];
            __syncthreads();
        }
        if (tid == 0) {
            out[0] = (float)(3.912023005428146 * dred[0] / 262144.0);
            g_count = 0;   // reset for next graph replay
        }
    }
}

// ---------------- launch --------------------------------------------------------
extern "C" void kernel_launch(void* const* d_in, const int* in_sizes, int n_in,
                              void* d_out, int out_size) {
    const float* x     = (const float*)d_in[0];   // (256,1024)
    const float* t     = (const float*)d_in[1];   // (256,1)
    const float* noise = (const float*)d_in[2];   // (256,1024)
    const float* W1    = (const float*)d_in[3];   // (1025,2048)
    const float* b1    = (const float*)d_in[4];   // (2048,)
    const float* W2    = (const float*)d_in[5];   // (2048,2048)
    const float* b2    = (const float*)d_in[6];   // (2048,)

    size_t smem = NSTAGE * STAGE_BYTES;   // 73728 > 48KB default -> opt-in required
    cudaFuncSetAttribute(gemm_k<1>, cudaFuncAttributeMaxDynamicSharedMemorySize, (int)smem);
    cudaFuncSetAttribute(gemm_k<2>, cudaFuncAttributeMaxDynamicSharedMemorySize, (int)smem);

    prep_k<<<1664, 256>>>(x, noise, t, W1, W2);

    dim3 g1(2048 / 64, BROWS / 64);       // (32, 4) = 128 CTAs
    gemm_k<1><<<g1, 256, smem>>>(DDIM, b1, t, W1 + (size_t)DDIM * HDIM);

    dim3 g2(2048 / 64, BROWS / 64, 2);    // (32, 4, 2) = 256 CTAs, split-K
    gemm_k<2><<<g2, 256, smem>>>(HDIM, b2, nullptr, nullptr);

    loss_k<<<1024, 256>>>(x, noise, (float*)d_out);
}